// round 3
// baseline (speedup 1.0000x reference)
#include <cuda_runtime.h>
#include <math.h>

#define T_STEPS 1000
#define BATCH   1024
#define IN_DIM  80
#define HID     128
#define OUT_DIM 10

// Scratch for precomputed input currents xw[t][b][h]  (512 MB device global — no alloc)
__device__ float g_xw[(size_t)T_STEPS * BATCH * HID];

// ---- packed f32x2 helpers (per-lane rounding == scalar fma.rn.f32 -> bitwise-safe) ----
__device__ __forceinline__ unsigned long long pk2(float lo, float hi) {
    unsigned long long r;
    asm("mov.b64 %0, {%1, %2};" : "=l"(r) : "f"(lo), "f"(hi));
    return r;
}
__device__ __forceinline__ unsigned long long ffma2(unsigned long long a,
                                                    unsigned long long b,
                                                    unsigned long long c) {
    unsigned long long d;
    asm("fma.rn.f32x2 %0, %1, %2, %3;" : "=l"(d) : "l"(a), "l"(b), "l"(c));
    return d;
}

// ---------------------------------------------------------------------------
// Kernel A: xw[row][h] = sum_{k=0..79} fma(x[row][k], w_in[h][k], acc)
// Sequential-k single-accumulator FMA chain (matches cublas/Eigen bitwise).
// CTA: 128 threads, tile 64 rows x 128 h, thread tile 8x8 via fma.rn.f32x2.
// ---------------------------------------------------------------------------
__global__ void __launch_bounds__(128) xw_gemm_kernel(const float* __restrict__ x,
                                                      const float* __restrict__ w_in,
                                                      float* __restrict__ xw) {
    __shared__ float xT[IN_DIM][64];    // [k][row]
    __shared__ float ws[IN_DIM][HID];   // [k][h]

    long row0 = (long)blockIdx.x * 64;
    int tid = threadIdx.x;

    for (int idx = tid; idx < 64 * IN_DIM; idx += 128) {
        int r = idx / IN_DIM, k = idx % IN_DIM;
        xT[k][r] = x[(row0 + r) * IN_DIM + k];
    }
    for (int idx = tid; idx < HID * IN_DIM; idx += 128) {
        int h = idx / IN_DIM, k = idx % IN_DIM;
        ws[k][h] = w_in[idx];
    }
    __syncthreads();

    int hg = tid & 15;         // 16 h-groups
    int rg = tid >> 4;         // 8 row-groups
    int h0 = hg * 8, r0 = rg * 8;

    unsigned long long acc[8][4];
#pragma unroll
    for (int r = 0; r < 8; ++r)
#pragma unroll
        for (int j = 0; j < 4; ++j) acc[r][j] = 0ull;

#pragma unroll 8
    for (int k = 0; k < IN_DIM; ++k) {
        float4 xa = *(const float4*)&xT[k][r0];
        float4 xb = *(const float4*)&xT[k][r0 + 4];
        float4 wa = *(const float4*)&ws[k][h0];
        float4 wb = *(const float4*)&ws[k][h0 + 4];
        unsigned long long w0 = pk2(wa.x, wa.y);
        unsigned long long w1 = pk2(wa.z, wa.w);
        unsigned long long w2 = pk2(wb.x, wb.y);
        unsigned long long w3 = pk2(wb.z, wb.w);
        float xr[8] = {xa.x, xa.y, xa.z, xa.w, xb.x, xb.y, xb.z, xb.w};
#pragma unroll
        for (int r = 0; r < 8; ++r) {
            unsigned long long xd = pk2(xr[r], xr[r]);
            acc[r][0] = ffma2(xd, w0, acc[r][0]);
            acc[r][1] = ffma2(xd, w1, acc[r][1]);
            acc[r][2] = ffma2(xd, w2, acc[r][2]);
            acc[r][3] = ffma2(xd, w3, acc[r][3]);
        }
    }

#pragma unroll
    for (int r = 0; r < 8; ++r) {
        unsigned long long* dst =
            (unsigned long long*)&xw[(row0 + r0 + r) * HID + h0];
#pragma unroll
        for (int j = 0; j < 4; ++j) dst[j] = acc[r][j];
    }
}

// ---------------------------------------------------------------------------
// Kernel B: sequential recurrence. 128 CTAs x 1024 threads.
// All elementwise math via __f*_rn intrinsics (NO fma contraction — XLA
// rounds mul and add separately). Sparse z@w_rec.T in ascending-j order is
// bitwise equal to the dense fma chain (fma(0,w,acc)==acc, fma(1,w,acc)==add).
// ---------------------------------------------------------------------------
__global__ void __launch_bounds__(1024) snn_rec_kernel(const float* __restrict__ xw,
                                                       const float* __restrict__ w_rec,
                                                       const float* __restrict__ w_out,
                                                       float* __restrict__ out) {
    extern __shared__ float smem[];
    float* wr_s = smem;                     // [128][128]: wr_s[j*128+h] = w_rec[h][j]
    float* wo_s = smem + HID * HID;         // [128][16] : wo_s[j*16+o]  = w_out[o][j]
    unsigned* mk_s = (unsigned*)(wo_s + HID * 16);   // [2][8][4] spike masks

    int tid = threadIdx.x;

    for (int idx = tid; idx < HID * HID; idx += 1024) {
        int j = idx >> 7, h = idx & 127;
        wr_s[idx] = w_rec[h * HID + j];
    }
    for (int idx = tid; idx < HID * 16; idx += 1024) {
        int j = idx >> 4, o = idx & 15;
        wo_s[idx] = (o < OUT_DIM) ? w_out[o * HID + j] : 0.0f;
    }
    __syncthreads();

    int g    = tid >> 7;       // batch group in CTA (0..7)
    int h    = tid & 127;      // hidden unit
    int wq   = h >> 5;         // warp-quarter within group
    int lane = tid & 31;
    int batch = blockIdx.x * 8 + g;

    float v  = 0.0f, cur = 0.0f;     // LIF state
    float vo = 0.0f, io  = 0.0f;     // LI readout state (lanes h<10)
    int buf = 0;

    const float* xw_b = xw + batch * HID + h;
    float xw_curr = xw_b[0];

    for (int t = 0; t < T_STEPS; ++t) {
        // --- LIF step: exact reference expression order, separate rounding ---
        float v_dec = __fadd_rn(v, __fmul_rn(0.1f, __fadd_rn(__fsub_rn(0.0f, v), cur)));
        float i_dec = __fsub_rn(cur, __fmul_rn(0.2f, cur));
        bool  z     = __fsub_rn(v_dec, 1.0f) > 0.0f;
        v = z ? 0.0f : v_dec;

        unsigned m = __ballot_sync(0xffffffffu, z);
        if (lane == 0) mk_s[(buf * 8 + g) * 4 + wq] = m;
        asm volatile("bar.sync %0, 128;" :: "r"(g + 1) : "memory");

        // prefetch next step's input current
        int tn = (t < T_STEPS - 1) ? t + 1 : t;
        float xw_next = xw_b[(size_t)tn * (BATCH * HID)];

        // sparse z @ w_rec.T (+ z @ w_out.T for output lanes), ascending j
        float rsum = 0.0f, osum = 0.0f;
#pragma unroll
        for (int w4 = 0; w4 < 4; ++w4) {
            unsigned mm = mk_s[(buf * 8 + g) * 4 + w4];
            while (mm) {
                int j = (w4 << 5) + (__ffs(mm) - 1);
                rsum = __fadd_rn(rsum, wr_s[(j << 7) + h]);
                if (h < OUT_DIM) osum = __fadd_rn(osum, wo_s[(j << 4) + h]);
                mm &= mm - 1;
            }
        }
        cur = __fadd_rn(__fadd_rn(i_dec, xw_curr), rsum);

        // --- LI readout ---
        if (h < OUT_DIM) {
            float ij = __fadd_rn(io, osum);
            vo = __fadd_rn(vo, __fmul_rn(0.1f, __fadd_rn(__fsub_rn(0.0f, vo), ij)));
            io = __fsub_rn(ij, __fmul_rn(0.2f, ij));
        }

        xw_curr = xw_next;
        buf ^= 1;
    }

    // --- log_softmax over 10 outputs per batch element ---
    if (h < OUT_DIM) wr_s[g * 32 + h] = vo;   // smem reuse
    __syncthreads();
    if (h < OUT_DIM) {
        float mx = -INFINITY;
#pragma unroll
        for (int o = 0; o < OUT_DIM; ++o) mx = fmaxf(mx, wr_s[g * 32 + o]);
        float s = 0.0f;
#pragma unroll
        for (int o = 0; o < OUT_DIM; ++o) s = __fadd_rn(s, expf(__fsub_rn(wr_s[g * 32 + o], mx)));
        out[batch * OUT_DIM + h] = __fsub_rn(__fsub_rn(vo, mx), logf(s));
    }
}

// ---------------------------------------------------------------------------
extern "C" void kernel_launch(void* const* d_in, const int* in_sizes, int n_in,
                              void* d_out, int out_size) {
    const float* x     = (const float*)d_in[0];
    const float* w_in  = (const float*)d_in[1];
    const float* w_rec = (const float*)d_in[2];
    const float* w_out = (const float*)d_in[3];
    float* out = (float*)d_out;

    float* xw = nullptr;
    cudaGetSymbolAddress((void**)&xw, g_xw);

    // Kernel A: 1,024,000 rows / 64 per CTA = 16000 CTAs
    xw_gemm_kernel<<<16000, 128>>>(x, w_in, xw);

    // Kernel B: sequential recurrence
    size_t smem_bytes = (size_t)(HID * HID + HID * 16) * sizeof(float)
                      + 2 * 8 * 4 * sizeof(unsigned);
    cudaFuncSetAttribute(snn_rec_kernel, cudaFuncAttributeMaxDynamicSharedMemorySize,
                         (int)smem_bytes);
    snn_rec_kernel<<<128, 1024, smem_bytes>>>(xw, w_rec, w_out, out);
}

// round 4
// speedup vs baseline: 1.7959x; 1.7959x over previous
#include <cuda_runtime.h>
#include <math.h>

#define T_STEPS 1000
#define BATCH   1024
#define IN_DIM  80
#define HID     128
#define OUT_DIM 10

typedef unsigned long long ull;

// Scratch: precomputed input currents xw[t][b][h] (512 MB) + transposed w_in
__device__ float g_xw[(size_t)T_STEPS * BATCH * HID];
__device__ float g_w_inT[IN_DIM * HID];   // w_inT[k*128+h] = w_in[h*80+k]

__device__ __forceinline__ ull pk2(float lo, float hi) {
    ull r; asm("mov.b64 %0, {%1, %2};" : "=l"(r) : "f"(lo), "f"(hi)); return r;
}
__device__ __forceinline__ ull ffma2(ull a, ull b, ull c) {
    ull d; asm("fma.rn.f32x2 %0, %1, %2, %3;" : "=l"(d) : "l"(a), "l"(b), "l"(c)); return d;
}

// ---------------------------------------------------------------------------
// Tiny transpose of w_in (40 KB, one-time)
// ---------------------------------------------------------------------------
__global__ void wtrans_kernel(const float* __restrict__ w_in, float* __restrict__ w_inT) {
    int idx = blockIdx.x * 256 + threadIdx.x;
    if (idx < IN_DIM * HID) {
        int k = idx >> 7, h = idx & 127;
        w_inT[idx] = w_in[h * IN_DIM + k];
    }
}

// ---------------------------------------------------------------------------
// Kernel A: xw[row][h] = fma-chain over k=0..79 of x[row][k]*w_in[h][k]
// (bitwise identical chain to R3: ascending k, single acc, fma.rn.f32x2)
// CTA: 128 threads, 64 rows x 128 h; thread = (rg: rows rg+8i) x (hg: h-pairs 2hg+32j)
// ---------------------------------------------------------------------------
__global__ void __launch_bounds__(128) xw_gemm_kernel(const float* __restrict__ x,
                                                      const float* __restrict__ w_inT,
                                                      float* __restrict__ xw) {
    extern __shared__ float sm[];
    float* xs  = sm;                 // [64][81] padded rows
    float* wsT = sm + 64 * 81;       // [80][128]

    long row0 = (long)blockIdx.x * 64;
    int tid = threadIdx.x;

    const float* xsrc = x + row0 * IN_DIM;
    for (int idx = tid; idx < 64 * IN_DIM; idx += 128) {
        int r = idx / IN_DIM, k = idx - r * IN_DIM;
        xs[r * 81 + k] = xsrc[idx];                 // coalesced LDG, near-consecutive STS
    }
    for (int idx = tid; idx < IN_DIM * HID; idx += 128)
        wsT[idx] = w_inT[idx];                      // coalesced both sides
    __syncthreads();

    int hg = tid & 15;        // h-pairs (2hg+32j, +1)
    int rg = tid >> 4;        // rows rg + 8i

    ull acc[8][4];
#pragma unroll
    for (int i = 0; i < 8; ++i)
#pragma unroll
        for (int j = 0; j < 4; ++j) acc[i][j] = 0ull;

#pragma unroll 10
    for (int k = 0; k < IN_DIM; ++k) {
        ull wp[4];
#pragma unroll
        for (int j = 0; j < 4; ++j)
            wp[j] = *(const ull*)&wsT[k * HID + 2 * hg + 32 * j];  // LDS.64, conflict-free
        float xv[8];
#pragma unroll
        for (int i = 0; i < 8; ++i)
            xv[i] = xs[(rg + 8 * i) * 81 + k];      // broadcast/conflict-free scalar LDS
#pragma unroll
        for (int i = 0; i < 8; ++i) {
            ull xd = pk2(xv[i], xv[i]);
#pragma unroll
            for (int j = 0; j < 4; ++j)
                acc[i][j] = ffma2(xd, wp[j], acc[i][j]);
        }
    }

#pragma unroll
    for (int i = 0; i < 8; ++i) {
        float* dst = &xw[(row0 + rg + 8 * i) * HID];
#pragma unroll
        for (int j = 0; j < 4; ++j)
            *(ull*)&dst[2 * hg + 32 * j] = acc[i][j];   // STG.64, coalesced
    }
}

// ---------------------------------------------------------------------------
// Kernel B: recurrence, warp-per-batch (NO barriers, NO smem masks).
// Lane l owns h = l, l+32, l+64, l+96. Ballot m (m=0..3) bit l = z[l+32m],
// so iterating m ascending + ffs ascending = ascending j (bitwise == R3 chain).
// wr_p[j][4l+m] permuted so each spike is one conflict-free LDS.128.
// ---------------------------------------------------------------------------
__global__ void __launch_bounds__(256) snn_rec_kernel(const float* __restrict__ xw,
                                                      const float* __restrict__ w_rec,
                                                      const float* __restrict__ w_out,
                                                      float* __restrict__ out) {
    extern __shared__ float smem[];
    float* wr_p = smem;              // [128][128] permuted: wr_p[j*128 + 4*(h&31) + (h>>5)] = w_rec[h][j]
    float* wo_s = smem + HID * HID;  // [128][16]: wo_s[j*16+o] = w_out[o][j]

    int tid = threadIdx.x;
    for (int idx = tid; idx < HID * HID; idx += 256) {
        int h = idx >> 7, j = idx & 127;
        wr_p[(j << 7) + ((h & 31) << 2) + (h >> 5)] = w_rec[idx];   // coalesced LDG
    }
    for (int idx = tid; idx < HID * 16; idx += 256) {
        int j = idx >> 4, o = idx & 15;
        wo_s[idx] = (o < OUT_DIM) ? w_out[o * HID + j] : 0.0f;
    }
    __syncthreads();

    int warp = tid >> 5, lane = tid & 31;
    int batch = blockIdx.x * 8 + warp;

    float v0 = 0.f, v1 = 0.f, v2 = 0.f, v3 = 0.f;
    float c0 = 0.f, c1 = 0.f, c2 = 0.f, c3 = 0.f;
    float vo = 0.f, io = 0.f;        // lanes 0..9: o = lane

    const float* xwp = xw + (size_t)batch * HID + lane;
    float x0 = xwp[0], x1 = xwp[32], x2 = xwp[64], x3 = xwp[96];

    for (int t = 0; t < T_STEPS; ++t) {
        // --- LIF (exact reference expression order, separate rounding) ---
        float vd0 = __fadd_rn(v0, __fmul_rn(0.1f, __fadd_rn(__fsub_rn(0.f, v0), c0)));
        float vd1 = __fadd_rn(v1, __fmul_rn(0.1f, __fadd_rn(__fsub_rn(0.f, v1), c1)));
        float vd2 = __fadd_rn(v2, __fmul_rn(0.1f, __fadd_rn(__fsub_rn(0.f, v2), c2)));
        float vd3 = __fadd_rn(v3, __fmul_rn(0.1f, __fadd_rn(__fsub_rn(0.f, v3), c3)));
        float id0 = __fsub_rn(c0, __fmul_rn(0.2f, c0));
        float id1 = __fsub_rn(c1, __fmul_rn(0.2f, c1));
        float id2 = __fsub_rn(c2, __fmul_rn(0.2f, c2));
        float id3 = __fsub_rn(c3, __fmul_rn(0.2f, c3));
        bool z0 = __fsub_rn(vd0, 1.0f) > 0.0f;
        bool z1 = __fsub_rn(vd1, 1.0f) > 0.0f;
        bool z2 = __fsub_rn(vd2, 1.0f) > 0.0f;
        bool z3 = __fsub_rn(vd3, 1.0f) > 0.0f;
        v0 = z0 ? 0.f : vd0;
        v1 = z1 ? 0.f : vd1;
        v2 = z2 ? 0.f : vd2;
        v3 = z3 ? 0.f : vd3;

        unsigned m0 = __ballot_sync(0xffffffffu, z0);
        unsigned m1 = __ballot_sync(0xffffffffu, z1);
        unsigned m2 = __ballot_sync(0xffffffffu, z2);
        unsigned m3 = __ballot_sync(0xffffffffu, z3);

        // prefetch next step's input current (coalesced scalar LDGs)
        const float* np = xwp + (size_t)(t < T_STEPS - 1 ? t + 1 : t) * (BATCH * HID);
        float n0 = np[0], n1 = np[32], n2 = np[64], n3 = np[96];

        // --- sparse z @ w_rec.T, ascending j (bitwise == dense chain) ---
        float r0 = 0.f, r1 = 0.f, r2 = 0.f, r3 = 0.f, os = 0.f;
#define SPIKES(MM, BASE)                                                        \
        while (MM) {                                                            \
            int b = __ffs(MM) - 1; MM &= MM - 1;                                \
            int j = (BASE) + b;                                                 \
            float4 w = *(const float4*)&wr_p[(j << 7) + (lane << 2)];           \
            r0 = __fadd_rn(r0, w.x); r1 = __fadd_rn(r1, w.y);                   \
            r2 = __fadd_rn(r2, w.z); r3 = __fadd_rn(r3, w.w);                   \
            if (lane < OUT_DIM) os = __fadd_rn(os, wo_s[(j << 4) + lane]);      \
        }
        SPIKES(m0, 0)
        SPIKES(m1, 32)
        SPIKES(m2, 64)
        SPIKES(m3, 96)
#undef SPIKES

        c0 = __fadd_rn(__fadd_rn(id0, x0), r0);
        c1 = __fadd_rn(__fadd_rn(id1, x1), r1);
        c2 = __fadd_rn(__fadd_rn(id2, x2), r2);
        c3 = __fadd_rn(__fadd_rn(id3, x3), r3);

        // --- LI readout (lanes 0..9, o = lane) ---
        if (lane < OUT_DIM) {
            float ij = __fadd_rn(io, os);
            vo = __fadd_rn(vo, __fmul_rn(0.1f, __fadd_rn(__fsub_rn(0.f, vo), ij)));
            io = __fsub_rn(ij, __fmul_rn(0.2f, ij));
        }

        x0 = n0; x1 = n1; x2 = n2; x3 = n3;
    }

    // --- log_softmax over 10 outputs (same ascending-o chains as R3) ---
    float mx = -INFINITY;
#pragma unroll
    for (int o = 0; o < OUT_DIM; ++o)
        mx = fmaxf(mx, __shfl_sync(0xffffffffu, vo, o));
    float s = 0.f;
#pragma unroll
    for (int o = 0; o < OUT_DIM; ++o)
        s = __fadd_rn(s, expf(__fsub_rn(__shfl_sync(0xffffffffu, vo, o), mx)));
    if (lane < OUT_DIM)
        out[batch * OUT_DIM + lane] = __fsub_rn(__fsub_rn(vo, mx), logf(s));
}

// ---------------------------------------------------------------------------
extern "C" void kernel_launch(void* const* d_in, const int* in_sizes, int n_in,
                              void* d_out, int out_size) {
    const float* x     = (const float*)d_in[0];
    const float* w_in  = (const float*)d_in[1];
    const float* w_rec = (const float*)d_in[2];
    const float* w_out = (const float*)d_in[3];
    float* out = (float*)d_out;

    float* xw = nullptr;
    float* w_inT = nullptr;
    cudaGetSymbolAddress((void**)&xw, g_xw);
    cudaGetSymbolAddress((void**)&w_inT, g_w_inT);

    wtrans_kernel<<<(IN_DIM * HID + 255) / 256, 256>>>(w_in, w_inT);

    size_t gemm_smem = (size_t)(64 * 81 + IN_DIM * HID) * sizeof(float);
    cudaFuncSetAttribute(xw_gemm_kernel, cudaFuncAttributeMaxDynamicSharedMemorySize,
                         (int)gemm_smem);
    xw_gemm_kernel<<<16000, 128, gemm_smem>>>(x, w_inT, xw);

    size_t rec_smem = (size_t)(HID * HID + HID * 16) * sizeof(float);
    cudaFuncSetAttribute(snn_rec_kernel, cudaFuncAttributeMaxDynamicSharedMemorySize,
                         (int)rec_smem);
    snn_rec_kernel<<<128, 256, rec_smem>>>(xw, w_rec, w_out, out);
}